// round 1
// baseline (speedup 1.0000x reference)
#include <cuda_runtime.h>
#include <cstdint>

#define NB 64
#define SL 510
#define NT 9
#define HID 768
#define FULLM 0xffffffffu

// Scratch (no dynamic allocation allowed)
__device__ float g_emiss[NB * SL * NT];
__device__ float g_partial[NB];

// ---------------------------------------------------------------------------
// Kernel A: emissions[b, s, t] = dot(hidden[b, s+1, :], weight[t, :]) + bias[t]
// 288 threads = 32 rows x 9 tags. Weight staged in smem with row pad 772
// (772 mod 32 = 4 -> tag rows land in different bank groups).
// ---------------------------------------------------------------------------
__global__ __launch_bounds__(288) void emis_kernel(
    const float* __restrict__ hidden,
    const float* __restrict__ weight,
    const float* __restrict__ bias) {
    __shared__ float ws[NT * 772];
    __shared__ float bs[NT];

    int tid = threadIdx.x;
    for (int i = tid; i < NT * HID; i += 288) {
        int t = i / HID, h = i - t * HID;
        ws[t * 772 + h] = weight[i];
    }
    if (tid < NT) bs[tid] = bias[tid];
    __syncthreads();

    int r = blockIdx.x * 32 + tid / NT;   // global (b, s) row, 0..32639
    int t = tid % NT;
    int b = r / SL;
    int sq = r - b * SL;

    const float4* hp = (const float4*)(hidden + (size_t)(b * 512 + sq + 1) * HID);
    const float4* wp = (const float4*)(ws + t * 772);

    float acc0 = 0.f, acc1 = 0.f;
#pragma unroll 8
    for (int k = 0; k < HID / 4; k += 2) {
        float4 h0 = hp[k];
        float4 w0 = wp[k];
        float4 h1 = hp[k + 1];
        float4 w1 = wp[k + 1];
        acc0 += h0.x * w0.x + h0.y * w0.y + h0.z * w0.z + h0.w * w0.w;
        acc1 += h1.x * w1.x + h1.y * w1.y + h1.z * w1.z + h1.w * w1.w;
    }
    g_emiss[r * NT + t] = acc0 + acc1 + bs[t];
}

// ---------------------------------------------------------------------------
// Kernel B: per-batch CRF (numerator score, log-domain forward, Viterbi +
// backtrack). One warp per batch; lanes 0..8 own tag j.
// ---------------------------------------------------------------------------
__global__ __launch_bounds__(32) void crf_kernel(
    const int* __restrict__ labels,
    const float* __restrict__ start_t,
    const float* __restrict__ end_t,
    const float* __restrict__ trans,
    float* __restrict__ out) {
    __shared__ float s_trans[NT * NT];
    __shared__ unsigned char hist[(SL - 1) * NT];

    int b = blockIdx.x;
    int lane = threadIdx.x;
    bool act = lane < NT;
    int lj = act ? lane : 0;

    for (int i = lane; i < NT * NT; i += 32) s_trans[i] = trans[i];

    float tr[NT];
#pragma unroll
    for (int i = 0; i < NT; i++) tr[i] = trans[i * NT + lj];  // column lj
    float startv = start_t[lj];
    float endv = end_t[lj];
    __syncwarp();

    const float* em_base = g_emiss + (size_t)b * SL * NT;
    const int* lbl = labels + b * 512;

    // step 0
    float em0 = em_base[lj];
    float alpha = startv + em0;   // denominator state (log domain), lane j
    float vs = alpha;             // viterbi state, lane j

    int lbl0 = lbl[1];
    int m0 = lbl0 >= 0;
    int tag0 = m0 ? lbl0 : 0;
    float score = __shfl_sync(FULLM, alpha, tag0);  // start[tag0] + em0[tag0]
    int prev = tag0;

    // prefetch step 1
    float em_next = em_base[NT + lj];
    int lbl_next = lbl[2];

    for (int s = 1; s < SL; ++s) {
        float emc = em_next;
        int lblc = lbl_next;
        if (s + 1 < SL) {
            em_next = em_base[(s + 1) * NT + lj];
            lbl_next = lbl[s + 2];
        }
        int m = lblc >= 0;
        int tg = m ? lblc : 0;

        // replicate state across lanes
        float a[NT], v[NT];
#pragma unroll
        for (int i = 0; i < NT; i++) {
            a[i] = __shfl_sync(FULLM, alpha, i);
            v[i] = __shfl_sync(FULLM, vs, i);
        }

        // denominator: logsumexp_i(a[i] + tr[i]) + em
        float x[NT];
#pragma unroll
        for (int i = 0; i < NT; i++) x[i] = a[i] + tr[i];
        float mx = fmaxf(fmaxf(fmaxf(x[0], x[1]), fmaxf(x[2], x[3])),
                         fmaxf(fmaxf(x[4], x[5]), fmaxf(x[6], fmaxf(x[7], x[8]))));
        float sm = __expf(x[0] - mx) + __expf(x[1] - mx) + __expf(x[2] - mx)
                 + __expf(x[3] - mx) + __expf(x[4] - mx) + __expf(x[5] - mx)
                 + __expf(x[6] - mx) + __expf(x[7] - mx) + __expf(x[8] - mx);
        float nxt = mx + __logf(sm) + emc;

        // viterbi: max/argmax_i (v[i] + tr[i]) (first index on ties)
        float best = v[0] + tr[0];
        int bi = 0;
#pragma unroll
        for (int i = 1; i < NT; i++) {
            float bv = v[i] + tr[i];
            if (bv > best) { best = bv; bi = i; }
        }
        float vn = best + emc;

        if (act) hist[(s - 1) * NT + lane] = (unsigned char)(m ? bi : lane);
        if (m) { alpha = nxt; vs = vn; }

        // numerator (uniform across lanes)
        float em_tg = __shfl_sync(FULLM, emc, tg);
        if (m) {
            score += s_trans[prev * NT + tg] + em_tg;
            prev = tg;
        }
    }
    __syncwarp();

    float numer = score + __shfl_sync(FULLM, endv, prev);

    float fa = alpha + endv;
    float fv = vs + endv;
    float af[NT], vf[NT];
#pragma unroll
    for (int i = 0; i < NT; i++) {
        af[i] = __shfl_sync(FULLM, fa, i);
        vf[i] = __shfl_sync(FULLM, fv, i);
    }
    float mx = fmaxf(fmaxf(fmaxf(af[0], af[1]), fmaxf(af[2], af[3])),
                     fmaxf(fmaxf(af[4], af[5]), fmaxf(af[6], fmaxf(af[7], af[8]))));
    float sm = __expf(af[0] - mx) + __expf(af[1] - mx) + __expf(af[2] - mx)
             + __expf(af[3] - mx) + __expf(af[4] - mx) + __expf(af[5] - mx)
             + __expf(af[6] - mx) + __expf(af[7] - mx) + __expf(af[8] - mx);
    float den = mx + __logf(sm);

    float vbest = vf[0];
    int last = 0;
#pragma unroll
    for (int i = 1; i < NT; i++) {
        if (vf[i] > vbest) { vbest = vf[i]; last = i; }
    }

    if (lane == 0) {
        g_partial[b] = numer - den;
        // backtrack: tags_out[SL-1] = last; tags_out[r] = hist[r][tags_out[r+1]]
        float* otag = out + 1 + (size_t)b * SL;
        int cur = last;
        otag[SL - 1] = (lbl[SL] >= 0) ? (float)cur : 0.f;
        for (int r = SL - 2; r >= 0; --r) {
            cur = hist[r * NT + cur];
            otag[r] = (lbl[r + 1] >= 0) ? (float)cur : 0.f;
        }
    }
}

// ---------------------------------------------------------------------------
// Kernel C: out[0] = -sum_b partial[b]
// ---------------------------------------------------------------------------
__global__ __launch_bounds__(32) void reduce_kernel(float* __restrict__ out) {
    int l = threadIdx.x;
    float v = g_partial[l] + g_partial[l + 32];
#pragma unroll
    for (int o = 16; o > 0; o >>= 1) v += __shfl_xor_sync(FULLM, v, o);
    if (l == 0) out[0] = -v;
}

// ---------------------------------------------------------------------------
extern "C" void kernel_launch(void* const* d_in, const int* in_sizes, int n_in,
                              void* d_out, int out_size) {
    const float* hidden  = (const float*)d_in[0];
    const int*   labels  = (const int*)d_in[1];
    const float* weight  = (const float*)d_in[2];
    const float* bias    = (const float*)d_in[3];
    const float* start_t = (const float*)d_in[4];
    const float* end_t   = (const float*)d_in[5];
    const float* trans   = (const float*)d_in[6];
    float* out = (float*)d_out;

    emis_kernel<<<(NB * SL) / 32, 288>>>(hidden, weight, bias);
    crf_kernel<<<NB, 32>>>(labels, start_t, end_t, trans, out);
    reduce_kernel<<<1, 32>>>(out);
}